// round 7
// baseline (speedup 1.0000x reference)
#include <cuda_runtime.h>
#include <cuda_bf16.h>

#define EMBED 1024
#define NHEADS 16
#define HDIM 64
#define SEQ 2048
#define NCLS 1000
#define GCHUNKS 16
#define MTOT 4096

#define BM 64
#define BN 128
#define BKE 32                    // K elems per smem stage
#define NIT (EMBED / BKE)         // 32
#define PK 40                     // padded row: 80B, ldmatrix conflict-free

#define OFF_AH 0
#define OFF_AL (BM * PK * 2)              // 5120
#define OFF_BH (2 * BM * PK * 2)          // 10240
#define OFF_BL (OFF_BH + BN * PK * 2)     // 20480
#define STAGEB (OFF_BL + BN * PK * 2)     // 30720
#define SMEM_BYTES (2 * STAGEB)           // 61440 -> 3 CTAs/SM

// ---------- scratch ----------
__device__ float g_P[MTOT * EMBED];
__device__ float g_G[32 * HDIM * HDIM];
__device__ float g_Gpart[GCHUNKS][32][HDIM * HDIM];
__device__ __nv_bfloat16 g_xh[MTOT * EMBED], g_xl[MTOT * EMBED];
__device__ __nv_bfloat16 g_wih[EMBED * EMBED], g_wil[EMBED * EMBED];
__device__ __nv_bfloat16 g_ph[MTOT * EMBED], g_pl[MTOT * EMBED];
__device__ __nv_bfloat16 g_b2h[2 * 1024 * EMBED], g_b2l[2 * 1024 * EMBED];

// ---------- helpers ----------
__device__ __forceinline__ unsigned smem_u32(const void* p) {
    unsigned a;
    asm("{ .reg .u64 t; cvta.to.shared.u64 t, %1; cvt.u32.u64 %0, t; }" : "=r"(a) : "l"(p));
    return a;
}
__device__ __forceinline__ void cpa16(unsigned s, const void* g) {
    asm volatile("cp.async.cg.shared.global [%0], [%1], 16;" :: "r"(s), "l"(g) : "memory");
}
#define CP_COMMIT() asm volatile("cp.async.commit_group;" ::: "memory")
#define CP_WAIT(n)  asm volatile("cp.async.wait_group %0;" :: "n"(n) : "memory")

#define LDSM4(r0, r1, r2, r3, a) \
    asm volatile("ldmatrix.sync.aligned.m8n8.x4.shared.b16 {%0,%1,%2,%3}, [%4];" \
        : "=r"(r0), "=r"(r1), "=r"(r2), "=r"(r3) : "r"(a))

#define MMA(c, a, b0v, b1v) \
    asm volatile("mma.sync.aligned.m16n8k16.row.col.f32.bf16.bf16.f32 " \
        "{%0,%1,%2,%3},{%4,%5,%6,%7},{%8,%9},{%0,%1,%2,%3};" \
        : "+f"((c)[0]), "+f"((c)[1]), "+f"((c)[2]), "+f"((c)[3]) \
        : "r"((a)[0]), "r"((a)[1]), "r"((a)[2]), "r"((a)[3]), "r"(b0v), "r"(b1v))

__device__ __forceinline__ unsigned pack_bf(float e0, float e1) {
    unsigned r;
    asm("cvt.rn.bf16x2.f32 %0, %1, %2;" : "=r"(r) : "f"(e1), "f"(e0));
    return r;
}

// ---------- fp32 -> (hi, lo) bf16 split ----------
__global__ void cvt_split(const float4* __restrict__ X, uint2* __restrict__ H,
                          uint2* __restrict__ L, int n4) {
    int i = blockIdx.x * blockDim.x + threadIdx.x;
    if (i >= n4) return;
    float4 x = X[i];
    unsigned h01 = pack_bf(x.x, x.y), h23 = pack_bf(x.z, x.w);
    float hx = __uint_as_float(h01 << 16), hy = __uint_as_float(h01 & 0xffff0000u);
    float hz = __uint_as_float(h23 << 16), hw = __uint_as_float(h23 & 0xffff0000u);
    unsigned l01 = pack_bf(x.x - hx, x.y - hy), l23 = pack_bf(x.z - hz, x.w - hw);
    H[i] = make_uint2(h01, h23);
    L[i] = make_uint2(l01, l23);
}

// ---------- bf16x3 mma.sync GEMM (64x128 tile, 3 CTAs/SM) ----------
__device__ __forceinline__ void load_stage(
    unsigned sbuf, int tid, int k0,
    const __nv_bfloat16* Ah, const __nv_bfloat16* Al,
    const __nv_bfloat16* Bh, const __nv_bfloat16* Bl,
    int m0, int n0)
{
    int row = tid >> 1;
    int half = tid & 1;
    unsigned soff = (unsigned)(row * PK + half * 16) * 2;
    // B: all 256 threads cover 128 rows x 32 k
    size_t gb = (size_t)(n0 + row) * EMBED + k0 + half * 16;
    cpa16(sbuf + OFF_BH + soff,      Bh + gb);
    cpa16(sbuf + OFF_BH + soff + 16, Bh + gb + 8);
    cpa16(sbuf + OFF_BL + soff,      Bl + gb);
    cpa16(sbuf + OFF_BL + soff + 16, Bl + gb + 8);
    // A: threads 0-127 cover 64 rows x 32 k
    if (tid < 128) {
        size_t ga = (size_t)(m0 + row) * EMBED + k0 + half * 16;
        cpa16(sbuf + OFF_AH + soff,      Ah + ga);
        cpa16(sbuf + OFF_AH + soff + 16, Ah + ga + 8);
        cpa16(sbuf + OFF_AL + soff,      Al + ga);
        cpa16(sbuf + OFF_AL + soff + 16, Al + ga + 8);
    }
}

__global__ __launch_bounds__(256, 3) void gemm_mma_bf16x3(
    const __nv_bfloat16* __restrict__ Ah, const __nv_bfloat16* __restrict__ Al,
    const __nv_bfloat16* __restrict__ BhBase, const __nv_bfloat16* __restrict__ BlBase,
    const float* __restrict__ bias, float* __restrict__ C,
    __nv_bfloat16* __restrict__ Sh, __nv_bfloat16* __restrict__ Sl,
    int N, long bStride)
{
    extern __shared__ __nv_bfloat16 sm[];
    int tid = threadIdx.x;
    int m0 = blockIdx.y * BM;
    int n0 = blockIdx.x * BN;
    unsigned sbase = smem_u32(sm);

    const __nv_bfloat16* Bh = BhBase + (size_t)(m0 >> 11) * bStride;
    const __nv_bfloat16* Bl = BlBase + (size_t)(m0 >> 11) * bStride;

    int wid = tid >> 5, lane = tid & 31;
    int wm = (wid & 1) * 32;     // 2 M-slots of 32
    int wn = (wid >> 1) * 32;    // 4 N-slots of 32

    float acc[2][4][4];
#pragma unroll
    for (int i = 0; i < 2; i++)
#pragma unroll
        for (int j = 0; j < 4; j++)
#pragma unroll
            for (int v = 0; v < 4; v++) acc[i][j][v] = 0.f;

    load_stage(sbase, tid, 0, Ah, Al, Bh, Bl, m0, n0);
    CP_COMMIT();

    unsigned a_lo = (unsigned)((wm + (lane & 15)) * PK + ((lane >> 4) << 3)) * 2;
    unsigned b_lo = (unsigned)((wn + (lane & 15)) * PK + ((lane >> 4) << 3)) * 2;

    for (int it = 0; it < NIT; it++) {
        if (it + 1 < NIT)
            load_stage(sbase + (unsigned)((it + 1) & 1) * STAGEB, tid,
                       (it + 1) * BKE, Ah, Al, Bh, Bl, m0, n0);
        CP_COMMIT();
        CP_WAIT(1);
        __syncthreads();

        unsigned sbuf = sbase + (unsigned)(it & 1) * STAGEB;
#pragma unroll
        for (int kk = 0; kk < 2; kk++) {
            unsigned ah[2][4], al[2][4], bb[2][4];
            unsigned ao = sbuf + a_lo + (unsigned)kk * 32;
            unsigned bo = sbuf + b_lo + (unsigned)kk * 32;

            // term 0: Ah * Bh
#pragma unroll
            for (int i = 0; i < 2; i++)
                LDSM4(ah[i][0], ah[i][1], ah[i][2], ah[i][3],
                      ao + OFF_AH + (unsigned)i * (16 * PK * 2));
#pragma unroll
            for (int L = 0; L < 2; L++)
                LDSM4(bb[L][0], bb[L][1], bb[L][2], bb[L][3],
                      bo + OFF_BH + (unsigned)L * (16 * PK * 2));
#pragma unroll
            for (int i = 0; i < 2; i++)
#pragma unroll
                for (int j = 0; j < 4; j++) {
                    int L = j >> 1, s = j & 1;
                    MMA(acc[i][j], ah[i], bb[L][s], bb[L][s + 2]);
                }
            // term 1: Al * Bh  (bb still holds Bh)
#pragma unroll
            for (int i = 0; i < 2; i++)
                LDSM4(al[i][0], al[i][1], al[i][2], al[i][3],
                      ao + OFF_AL + (unsigned)i * (16 * PK * 2));
#pragma unroll
            for (int i = 0; i < 2; i++)
#pragma unroll
                for (int j = 0; j < 4; j++) {
                    int L = j >> 1, s = j & 1;
                    MMA(acc[i][j], al[i], bb[L][s], bb[L][s + 2]);
                }
            // term 2: Ah * Bl  (reuse bb registers for Bl)
#pragma unroll
            for (int L = 0; L < 2; L++)
                LDSM4(bb[L][0], bb[L][1], bb[L][2], bb[L][3],
                      bo + OFF_BL + (unsigned)L * (16 * PK * 2));
#pragma unroll
            for (int i = 0; i < 2; i++)
#pragma unroll
                for (int j = 0; j < 4; j++) {
                    int L = j >> 1, s = j & 1;
                    MMA(acc[i][j], ah[i], bb[L][s], bb[L][s + 2]);
                }
        }
        __syncthreads();
    }

    // epilogue
    int r = lane >> 2, c2 = (lane & 3) * 2;
#pragma unroll
    for (int i = 0; i < 2; i++) {
        int m = m0 + wm + i * 16 + r;
        float* C0 = C + (size_t)m * N;
        float* C1 = C0 + (size_t)8 * N;
        unsigned* S0h = Sh ? (unsigned*)(Sh + (size_t)m * EMBED) : nullptr;
        unsigned* S0l = Sh ? (unsigned*)(Sl + (size_t)m * EMBED) : nullptr;
        unsigned* S1h = Sh ? (unsigned*)(Sh + (size_t)(m + 8) * EMBED) : nullptr;
        unsigned* S1l = Sh ? (unsigned*)(Sl + (size_t)(m + 8) * EMBED) : nullptr;
#pragma unroll
        for (int j = 0; j < 4; j++) {
            int n = n0 + wn + j * 8 + c2;
            float bv0 = (n < N) ? bias[n] : 0.f;
            float bv1 = (n + 1 < N) ? bias[n + 1] : 0.f;
            float v00 = acc[i][j][0] + bv0, v01 = acc[i][j][1] + bv1;
            float v10 = acc[i][j][2] + bv0, v11 = acc[i][j][3] + bv1;
            if (n < N)     { C0[n] = v00; C1[n] = v10; }
            if (n + 1 < N) { C0[n + 1] = v01; C1[n + 1] = v11; }
            if (Sh) {
                unsigned h0 = pack_bf(v00, v01);
                unsigned h1 = pack_bf(v10, v11);
                float h0x = __uint_as_float(h0 << 16), h0y = __uint_as_float(h0 & 0xffff0000u);
                float h1x = __uint_as_float(h1 << 16), h1y = __uint_as_float(h1 & 0xffff0000u);
                S0h[n >> 1] = h0;
                S1h[n >> 1] = h1;
                S0l[n >> 1] = pack_bf(v00 - h0x, v01 - h0y);
                S1l[n >> 1] = pack_bf(v10 - h1x, v11 - h1y);
            }
        }
    }
}

// ---------- Gram kernels ----------
__global__ __launch_bounds__(256) void head_gram_part(
    const float* __restrict__ P, float* __restrict__ Gpart)
{
    int bh = blockIdx.x;
    int chunk = blockIdx.y;
    int b = bh >> 4;
    int h = bh & 15;
    const float* Pb = P + (size_t)b * SEQ * EMBED + h * HDIM;
    int sBeg = chunk * (SEQ / GCHUNKS);

    __shared__ float Ps[64][65];
    int tid = threadIdx.x;
    int j  = tid & 63;
    int i0 = (tid >> 6) << 4;

    float acc[16];
#pragma unroll
    for (int ii = 0; ii < 16; ii++) acc[ii] = 0.f;

    for (int s0 = sBeg; s0 < sBeg + SEQ / GCHUNKS; s0 += 64) {
        __syncthreads();
#pragma unroll
        for (int v = 0; v < 4; v++) {
            int idx = tid + v * 256;
            int rr = idx >> 4;
            int c = (idx & 15) << 2;
            float4 p4 = *(const float4*)(Pb + (size_t)(s0 + rr) * EMBED + c);
            Ps[rr][c + 0] = p4.x; Ps[rr][c + 1] = p4.y;
            Ps[rr][c + 2] = p4.z; Ps[rr][c + 3] = p4.w;
        }
        __syncthreads();
#pragma unroll 4
        for (int s = 0; s < 64; s++) {
            float bj = Ps[s][j];
#pragma unroll
            for (int ii = 0; ii < 16; ii++)
                acc[ii] += Ps[s][i0 + ii] * bj;
        }
    }

    float* Gp = Gpart + ((size_t)chunk * 32 + bh) * (HDIM * HDIM);
#pragma unroll
    for (int ii = 0; ii < 16; ii++)
        Gp[(i0 + ii) * HDIM + j] = acc[ii];
}

__global__ void gram_reduce(const float* __restrict__ Gpart,
                            float* __restrict__ G, float scale)
{
    int idx = blockIdx.x * blockDim.x + threadIdx.x;
    if (idx >= 32 * HDIM * HDIM) return;
    float s = 0.f;
#pragma unroll
    for (int c = 0; c < GCHUNKS; c++)
        s += Gpart[(size_t)c * 32 * HDIM * HDIM + idx];
    G[idx] = s * scale;
}

// ---------- fused B2 build ----------
__global__ __launch_bounds__(256) void w2_build(
    const float* __restrict__ Wo, const float* __restrict__ G,
    __nv_bfloat16* __restrict__ B2h, __nv_bfloat16* __restrict__ B2l)
{
    int c0 = blockIdx.x * 64;
    int h  = blockIdx.y;
    int b  = blockIdx.z;
    const float* Gh = G + (size_t)(b * NHEADS + h) * HDIM * HDIM;

    __shared__ float Gs[64][65];
    __shared__ float Ws[64][65];
    int tid = threadIdx.x;

#pragma unroll
    for (int v = 0; v < 4; v++) {
        int idx = tid + v * 256;
        int rr = idx >> 4;
        int c = (idx & 15) << 2;
        float4 g4 = *(const float4*)(Gh + rr * HDIM + c);
        Gs[rr][c + 0] = g4.x; Gs[rr][c + 1] = g4.y;
        Gs[rr][c + 2] = g4.z; Gs[rr][c + 3] = g4.w;
        float4 w4 = make_float4(0.f, 0.f, 0.f, 0.f);
        if (c0 + rr < NCLS)
            w4 = *(const float4*)(Wo + (size_t)(c0 + rr) * EMBED + h * HDIM + c);
        Ws[rr][c + 0] = w4.x; Ws[rr][c + 1] = w4.y;
        Ws[rr][c + 2] = w4.z; Ws[rr][c + 3] = w4.w;
    }
    __syncthreads();

    int j  = tid & 63;
    int i0 = (tid >> 6) << 4;
    float acc[16];
#pragma unroll
    for (int ii = 0; ii < 16; ii++) acc[ii] = 0.f;

#pragma unroll 4
    for (int k = 0; k < 64; k++) {
        float g = Gs[k][j];
#pragma unroll
        for (int ii = 0; ii < 16; ii++)
            acc[ii] += Ws[i0 + ii][k] * g;
    }

#pragma unroll
    for (int ii = 0; ii < 16; ii++) {
        size_t o = (size_t)b * 1024 * EMBED + (size_t)(c0 + i0 + ii) * EMBED + h * HDIM + j;
        float v = acc[ii];
        __nv_bfloat16 hi = __float2bfloat16(v);
        B2h[o] = hi;
        B2l[o] = __float2bfloat16(v - __bfloat162float(hi));
    }
}

// ---------- launch ----------
extern "C" void kernel_launch(void* const* d_in, const int* in_sizes, int n_in,
                              void* d_out, int out_size)
{
    const float* x     = (const float*)d_in[0];
    const float* W_in  = (const float*)d_in[1];
    const float* b_in  = (const float*)d_in[2];
    const float* W_out = (const float*)d_in[3];
    const float* b_out = (const float*)d_in[4];
    float* out = (float*)d_out;

    int M = in_sizes[0] / EMBED;   // 4096

    float *P, *G, *Gp;
    cudaGetSymbolAddress((void**)&P, g_P);
    cudaGetSymbolAddress((void**)&G, g_G);
    cudaGetSymbolAddress((void**)&Gp, g_Gpart);
    __nv_bfloat16 *xh, *xl, *wih, *wil, *ph, *pl, *b2h, *b2l;
    cudaGetSymbolAddress((void**)&xh, g_xh);
    cudaGetSymbolAddress((void**)&xl, g_xl);
    cudaGetSymbolAddress((void**)&wih, g_wih);
    cudaGetSymbolAddress((void**)&wil, g_wil);
    cudaGetSymbolAddress((void**)&ph, g_ph);
    cudaGetSymbolAddress((void**)&pl, g_pl);
    cudaGetSymbolAddress((void**)&b2h, g_b2h);
    cudaGetSymbolAddress((void**)&b2l, g_b2l);

    cudaFuncSetAttribute(gemm_mma_bf16x3, cudaFuncAttributeMaxDynamicSharedMemorySize, SMEM_BYTES);

    dim3 blk(256);

    cvt_split<<<(M * EMBED / 4) / 256, blk>>>((const float4*)x, (uint2*)xh, (uint2*)xl, M * EMBED / 4);
    cvt_split<<<(EMBED * EMBED / 4) / 256, blk>>>((const float4*)W_in, (uint2*)wih, (uint2*)wil, EMBED * EMBED / 4);

    // 1) P = X @ W_in^T + b_in  (fp32 P + hi/lo split)
    gemm_mma_bf16x3<<<dim3(EMBED / BN, M / BM), blk, SMEM_BYTES>>>(
        xh, xl, wih, wil, b_in, P, ph, pl, EMBED, 0);

    // 2) G = scale * P_h^T P_h
    head_gram_part<<<dim3((M / SEQ) * NHEADS, GCHUNKS), blk>>>(P, Gp);
    gram_reduce<<<(32 * HDIM * HDIM + 255) / 256, blk>>>(Gp, G, 1.0f / 32.0f);

    // 3) B2[b] = blockdiag(G) @ W_out^T
    w2_build<<<dim3(1024 / 64, NHEADS, M / SEQ), blk>>>(W_out, G, b2h, b2l);

    // 4) out = P @ B2[b]^T + b_out
    gemm_mma_bf16x3<<<dim3(1024 / BN, M / BM), blk, SMEM_BYTES>>>(
        ph, pl, b2h, b2l, b_out, out, nullptr, nullptr, NCLS, (long)1024 * EMBED);
}

// round 8
// speedup vs baseline: 1.1139x; 1.1139x over previous
#include <cuda_runtime.h>
#include <cuda_bf16.h>

#define EMBED 1024
#define NHEADS 16
#define HDIM 64
#define SEQ 2048
#define NCLS 1000
#define GCHUNKS 16
#define MTOT 4096

#define BM 128
#define BN 128
#define BKE 32                    // K elems per smem stage
#define NIT (EMBED / BKE)         // 32
#define PK 40                     // padded row: 80B, ldmatrix conflict-free
#define TSZ (BM * PK)
#define STAGEB (4 * TSZ * 2)      // {Ah,Al,Bh,Bl} = 40960 B
#define SMEM_BYTES (2 * STAGEB)   // 81920 -> 2 CTAs/SM

// ---------- scratch ----------
__device__ float g_P[MTOT * EMBED];
__device__ float g_G[32 * HDIM * HDIM];
__device__ float g_Gpart[GCHUNKS][32][HDIM * HDIM];
__device__ __nv_bfloat16 g_xh[MTOT * EMBED], g_xl[MTOT * EMBED];
__device__ __nv_bfloat16 g_wih[EMBED * EMBED], g_wil[EMBED * EMBED];
__device__ __nv_bfloat16 g_ph[MTOT * EMBED], g_pl[MTOT * EMBED];
__device__ __nv_bfloat16 g_b2h[2 * 1024 * EMBED], g_b2l[2 * 1024 * EMBED];

// ---------- helpers ----------
__device__ __forceinline__ unsigned smem_u32(const void* p) {
    unsigned a;
    asm("{ .reg .u64 t; cvta.to.shared.u64 t, %1; cvt.u32.u64 %0, t; }" : "=r"(a) : "l"(p));
    return a;
}
__device__ __forceinline__ void cpa16(unsigned s, const void* g) {
    asm volatile("cp.async.cg.shared.global [%0], [%1], 16;" :: "r"(s), "l"(g) : "memory");
}
#define CP_COMMIT() asm volatile("cp.async.commit_group;" ::: "memory")
#define CP_WAIT(n)  asm volatile("cp.async.wait_group %0;" :: "n"(n) : "memory")

#define LDSM4(r0, r1, r2, r3, a) \
    asm volatile("ldmatrix.sync.aligned.m8n8.x4.shared.b16 {%0,%1,%2,%3}, [%4];" \
        : "=r"(r0), "=r"(r1), "=r"(r2), "=r"(r3) : "r"(a))

#define MMA(c, a, b0v, b1v) \
    asm volatile("mma.sync.aligned.m16n8k16.row.col.f32.bf16.bf16.f32 " \
        "{%0,%1,%2,%3},{%4,%5,%6,%7},{%8,%9},{%0,%1,%2,%3};" \
        : "+f"((c)[0]), "+f"((c)[1]), "+f"((c)[2]), "+f"((c)[3]) \
        : "r"((a)[0]), "r"((a)[1]), "r"((a)[2]), "r"((a)[3]), "r"(b0v), "r"(b1v))

__device__ __forceinline__ unsigned pack_bf(float e0, float e1) {
    unsigned r;
    asm("cvt.rn.bf16x2.f32 %0, %1, %2;" : "=r"(r) : "f"(e1), "f"(e0));
    return r;
}

// ---------- fp32 -> (hi, lo) bf16 split ----------
__global__ void cvt_split(const float4* __restrict__ X, uint2* __restrict__ H,
                          uint2* __restrict__ L, int n4) {
    int i = blockIdx.x * blockDim.x + threadIdx.x;
    if (i >= n4) return;
    float4 x = X[i];
    unsigned h01 = pack_bf(x.x, x.y), h23 = pack_bf(x.z, x.w);
    float hx = __uint_as_float(h01 << 16), hy = __uint_as_float(h01 & 0xffff0000u);
    float hz = __uint_as_float(h23 << 16), hw = __uint_as_float(h23 & 0xffff0000u);
    unsigned l01 = pack_bf(x.x - hx, x.y - hy), l23 = pack_bf(x.z - hz, x.w - hw);
    H[i] = make_uint2(h01, h23);
    L[i] = make_uint2(l01, l23);
}

// ---------- bf16x3 mma.sync GEMM (R6 tiling, race-fixed pipeline) ----------
__device__ __forceinline__ void load_stage(
    unsigned sbuf, int tid, int k0,
    const __nv_bfloat16* Ah, const __nv_bfloat16* Al,
    const __nv_bfloat16* Bh, const __nv_bfloat16* Bl,
    int m0, int n0)
{
    int row = tid >> 1;
    int half = tid & 1;
    unsigned soff = (unsigned)(row * PK + half * 16) * 2;
    size_t ga = (size_t)(m0 + row) * EMBED + k0 + half * 16;
    size_t gb = (size_t)(n0 + row) * EMBED + k0 + half * 16;
    cpa16(sbuf + soff,                Ah + ga);
    cpa16(sbuf + soff + 16,           Ah + ga + 8);
    cpa16(sbuf + TSZ * 2 + soff,      Al + ga);
    cpa16(sbuf + TSZ * 2 + soff + 16, Al + ga + 8);
    cpa16(sbuf + TSZ * 4 + soff,      Bh + gb);
    cpa16(sbuf + TSZ * 4 + soff + 16, Bh + gb + 8);
    cpa16(sbuf + TSZ * 6 + soff,      Bl + gb);
    cpa16(sbuf + TSZ * 6 + soff + 16, Bl + gb + 8);
}

__global__ __launch_bounds__(256, 2) void gemm_mma_bf16x3(
    const __nv_bfloat16* __restrict__ Ah, const __nv_bfloat16* __restrict__ Al,
    const __nv_bfloat16* __restrict__ BhBase, const __nv_bfloat16* __restrict__ BlBase,
    const float* __restrict__ bias, float* __restrict__ C,
    __nv_bfloat16* __restrict__ Sh, __nv_bfloat16* __restrict__ Sl,
    int N, long bStride)
{
    extern __shared__ __nv_bfloat16 sm[];
    int tid = threadIdx.x;
    int m0 = blockIdx.y * BM;
    int n0 = blockIdx.x * BN;
    unsigned sbase = smem_u32(sm);

    const __nv_bfloat16* Bh = BhBase + (size_t)(m0 >> 11) * bStride;
    const __nv_bfloat16* Bl = BlBase + (size_t)(m0 >> 11) * bStride;

    int wid = tid >> 5, lane = tid & 31;
    int wm = (wid & 1) * 64;
    int wn = (wid >> 1) * 32;

    float acc[4][4][4];
#pragma unroll
    for (int i = 0; i < 4; i++)
#pragma unroll
        for (int j = 0; j < 4; j++)
#pragma unroll
            for (int v = 0; v < 4; v++) acc[i][j][v] = 0.f;

    load_stage(sbase, tid, 0, Ah, Al, Bh, Bl, m0, n0);
    CP_COMMIT();

    unsigned a_lo = (unsigned)((wm + (lane & 15)) * PK + ((lane >> 4) << 3)) * 2;
    unsigned b_lo = (unsigned)((wn + (lane & 15)) * PK + ((lane >> 4) << 3)) * 2;

    for (int it = 0; it < NIT; it++) {
        // load(it) is the only pending group -> wait for it fully
        CP_WAIT(0);
        // all warps done reading the buffer load(it+1) will overwrite
        __syncthreads();
        if (it + 1 < NIT) {
            load_stage(sbase + (unsigned)((it + 1) & 1) * STAGEB, tid,
                       (it + 1) * BKE, Ah, Al, Bh, Bl, m0, n0);
            CP_COMMIT();
        }

        unsigned sbuf = sbase + (unsigned)(it & 1) * STAGEB;
#pragma unroll
        for (int kk = 0; kk < 2; kk++) {
            unsigned ah[4][4], al[4][4], bb[2][4];
            unsigned ao = sbuf + a_lo + (unsigned)kk * 32;
            unsigned bo = sbuf + b_lo + (unsigned)kk * 32;

            // term 0: Ah * Bh
#pragma unroll
            for (int i = 0; i < 4; i++)
                LDSM4(ah[i][0], ah[i][1], ah[i][2], ah[i][3], ao + (unsigned)i * (16 * PK * 2));
#pragma unroll
            for (int L = 0; L < 2; L++)
                LDSM4(bb[L][0], bb[L][1], bb[L][2], bb[L][3], bo + TSZ * 4 + (unsigned)L * (16 * PK * 2));
#pragma unroll
            for (int i = 0; i < 4; i++)
#pragma unroll
                for (int j = 0; j < 4; j++) {
                    int L = j >> 1, s = j & 1;
                    MMA(acc[i][j], ah[i], bb[L][s], bb[L][s + 2]);
                }
            // term 1: Al * Bh  (bb still holds Bh)
#pragma unroll
            for (int i = 0; i < 4; i++)
                LDSM4(al[i][0], al[i][1], al[i][2], al[i][3], ao + TSZ * 2 + (unsigned)i * (16 * PK * 2));
#pragma unroll
            for (int i = 0; i < 4; i++)
#pragma unroll
                for (int j = 0; j < 4; j++) {
                    int L = j >> 1, s = j & 1;
                    MMA(acc[i][j], al[i], bb[L][s], bb[L][s + 2]);
                }
            // term 2: Ah * Bl  (reuse bb for Bl)
#pragma unroll
            for (int L = 0; L < 2; L++)
                LDSM4(bb[L][0], bb[L][1], bb[L][2], bb[L][3], bo + TSZ * 6 + (unsigned)L * (16 * PK * 2));
#pragma unroll
            for (int i = 0; i < 4; i++)
#pragma unroll
                for (int j = 0; j < 4; j++) {
                    int L = j >> 1, s = j & 1;
                    MMA(acc[i][j], ah[i], bb[L][s], bb[L][s + 2]);
                }
        }
    }

    // epilogue
    int r = lane >> 2, c2 = (lane & 3) * 2;
#pragma unroll
    for (int i = 0; i < 4; i++) {
        int m = m0 + wm + i * 16 + r;
        float* C0 = C + (size_t)m * N;
        float* C1 = C0 + (size_t)8 * N;
        unsigned* S0h = Sh ? (unsigned*)(Sh + (size_t)m * EMBED) : nullptr;
        unsigned* S0l = Sh ? (unsigned*)(Sl + (size_t)m * EMBED) : nullptr;
        unsigned* S1h = Sh ? (unsigned*)(Sh + (size_t)(m + 8) * EMBED) : nullptr;
        unsigned* S1l = Sh ? (unsigned*)(Sl + (size_t)(m + 8) * EMBED) : nullptr;
#pragma unroll
        for (int j = 0; j < 4; j++) {
            int n = n0 + wn + j * 8 + c2;
            float bv0 = (n < N) ? bias[n] : 0.f;
            float bv1 = (n + 1 < N) ? bias[n + 1] : 0.f;
            float v00 = acc[i][j][0] + bv0, v01 = acc[i][j][1] + bv1;
            float v10 = acc[i][j][2] + bv0, v11 = acc[i][j][3] + bv1;
            if (n < N)     { C0[n] = v00; C1[n] = v10; }
            if (n + 1 < N) { C0[n + 1] = v01; C1[n + 1] = v11; }
            if (Sh) {
                unsigned h0 = pack_bf(v00, v01);
                unsigned h1 = pack_bf(v10, v11);
                float h0x = __uint_as_float(h0 << 16), h0y = __uint_as_float(h0 & 0xffff0000u);
                float h1x = __uint_as_float(h1 << 16), h1y = __uint_as_float(h1 & 0xffff0000u);
                S0h[n >> 1] = h0;
                S1h[n >> 1] = h1;
                S0l[n >> 1] = pack_bf(v00 - h0x, v01 - h0y);
                S1l[n >> 1] = pack_bf(v10 - h1x, v11 - h1y);
            }
        }
    }
}

// ---------- Gram: 4x4 register blocking, float4 LDS ----------
__global__ __launch_bounds__(256) void head_gram_part(
    const float* __restrict__ P, float* __restrict__ Gpart)
{
    int bh = blockIdx.x;
    int chunk = blockIdx.y;
    int b = bh >> 4;
    int h = bh & 15;
    const float* Pb = P + (size_t)b * SEQ * EMBED + h * HDIM;
    int sBeg = chunk * (SEQ / GCHUNKS);

    __shared__ float Ps[64][68];   // 272B rows: 16B-aligned, column-broadcast friendly
    int tid = threadIdx.x;
    int j0 = (tid & 15) << 2;      // 16 j-blocks of 4
    int i0 = (tid >> 4) << 2;      // 16 i-blocks of 4

    float acc[4][4];
#pragma unroll
    for (int i = 0; i < 4; i++)
#pragma unroll
        for (int j = 0; j < 4; j++) acc[i][j] = 0.f;

    for (int s0 = sBeg; s0 < sBeg + SEQ / GCHUNKS; s0 += 64) {
        __syncthreads();
#pragma unroll
        for (int v = 0; v < 4; v++) {
            int idx = tid + v * 256;
            int rr = idx >> 4;
            int c = (idx & 15) << 2;
            float4 p4 = *(const float4*)(Pb + (size_t)(s0 + rr) * EMBED + c);
            *(float4*)&Ps[rr][c] = p4;
        }
        __syncthreads();
#pragma unroll 8
        for (int s = 0; s < 64; s++) {
            float4 a4 = *(const float4*)&Ps[s][i0];
            float4 b4 = *(const float4*)&Ps[s][j0];
            float a[4] = {a4.x, a4.y, a4.z, a4.w};
            float bj[4] = {b4.x, b4.y, b4.z, b4.w};
#pragma unroll
            for (int i = 0; i < 4; i++)
#pragma unroll
                for (int j = 0; j < 4; j++)
                    acc[i][j] += a[i] * bj[j];
        }
    }

    float* Gp = Gpart + ((size_t)chunk * 32 + bh) * (HDIM * HDIM);
#pragma unroll
    for (int i = 0; i < 4; i++) {
        float4 o = make_float4(acc[i][0], acc[i][1], acc[i][2], acc[i][3]);
        *(float4*)&Gp[(i0 + i) * HDIM + j0] = o;
    }
}

__global__ void gram_reduce(const float* __restrict__ Gpart,
                            float* __restrict__ G, float scale)
{
    int idx = blockIdx.x * blockDim.x + threadIdx.x;
    if (idx >= 32 * HDIM * HDIM) return;
    float s = 0.f;
#pragma unroll
    for (int c = 0; c < GCHUNKS; c++)
        s += Gpart[(size_t)c * 32 * HDIM * HDIM + idx];
    G[idx] = s * scale;
}

// ---------- fused B2 build ----------
__global__ __launch_bounds__(256) void w2_build(
    const float* __restrict__ Wo, const float* __restrict__ G,
    __nv_bfloat16* __restrict__ B2h, __nv_bfloat16* __restrict__ B2l)
{
    int c0 = blockIdx.x * 64;
    int h  = blockIdx.y;
    int b  = blockIdx.z;
    const float* Gh = G + (size_t)(b * NHEADS + h) * HDIM * HDIM;

    __shared__ float Gs[64][65];
    __shared__ float Ws[64][65];
    int tid = threadIdx.x;

#pragma unroll
    for (int v = 0; v < 4; v++) {
        int idx = tid + v * 256;
        int rr = idx >> 4;
        int c = (idx & 15) << 2;
        float4 g4 = *(const float4*)(Gh + rr * HDIM + c);
        Gs[rr][c + 0] = g4.x; Gs[rr][c + 1] = g4.y;
        Gs[rr][c + 2] = g4.z; Gs[rr][c + 3] = g4.w;
        float4 w4 = make_float4(0.f, 0.f, 0.f, 0.f);
        if (c0 + rr < NCLS)
            w4 = *(const float4*)(Wo + (size_t)(c0 + rr) * EMBED + h * HDIM + c);
        Ws[rr][c + 0] = w4.x; Ws[rr][c + 1] = w4.y;
        Ws[rr][c + 2] = w4.z; Ws[rr][c + 3] = w4.w;
    }
    __syncthreads();

    int j  = tid & 63;
    int i0 = (tid >> 6) << 4;
    float acc[16];
#pragma unroll
    for (int ii = 0; ii < 16; ii++) acc[ii] = 0.f;

#pragma unroll 4
    for (int k = 0; k < 64; k++) {
        float g = Gs[k][j];
#pragma unroll
        for (int ii = 0; ii < 16; ii++)
            acc[ii] += Ws[i0 + ii][k] * g;
    }

#pragma unroll
    for (int ii = 0; ii < 16; ii++) {
        size_t o = (size_t)b * 1024 * EMBED + (size_t)(c0 + i0 + ii) * EMBED + h * HDIM + j;
        float v = acc[ii];
        __nv_bfloat16 hi = __float2bfloat16(v);
        B2h[o] = hi;
        B2l[o] = __float2bfloat16(v - __bfloat162float(hi));
    }
}

// ---------- launch ----------
extern "C" void kernel_launch(void* const* d_in, const int* in_sizes, int n_in,
                              void* d_out, int out_size)
{
    const float* x     = (const float*)d_in[0];
    const float* W_in  = (const float*)d_in[1];
    const float* b_in  = (const float*)d_in[2];
    const float* W_out = (const float*)d_in[3];
    const float* b_out = (const float*)d_in[4];
    float* out = (float*)d_out;

    int M = in_sizes[0] / EMBED;   // 4096

    float *P, *G, *Gp;
    cudaGetSymbolAddress((void**)&P, g_P);
    cudaGetSymbolAddress((void**)&G, g_G);
    cudaGetSymbolAddress((void**)&Gp, g_Gpart);
    __nv_bfloat16 *xh, *xl, *wih, *wil, *ph, *pl, *b2h, *b2l;
    cudaGetSymbolAddress((void**)&xh, g_xh);
    cudaGetSymbolAddress((void**)&xl, g_xl);
    cudaGetSymbolAddress((void**)&wih, g_wih);
    cudaGetSymbolAddress((void**)&wil, g_wil);
    cudaGetSymbolAddress((void**)&ph, g_ph);
    cudaGetSymbolAddress((void**)&pl, g_pl);
    cudaGetSymbolAddress((void**)&b2h, g_b2h);
    cudaGetSymbolAddress((void**)&b2l, g_b2l);

    cudaFuncSetAttribute(gemm_mma_bf16x3, cudaFuncAttributeMaxDynamicSharedMemorySize, SMEM_BYTES);

    dim3 blk(256);

    cvt_split<<<(M * EMBED / 4) / 256, blk>>>((const float4*)x, (uint2*)xh, (uint2*)xl, M * EMBED / 4);
    cvt_split<<<(EMBED * EMBED / 4) / 256, blk>>>((const float4*)W_in, (uint2*)wih, (uint2*)wil, EMBED * EMBED / 4);

    // 1) P = X @ W_in^T + b_in  (fp32 P + hi/lo split)
    gemm_mma_bf16x3<<<dim3(EMBED / BN, M / BM), blk, SMEM_BYTES>>>(
        xh, xl, wih, wil, b_in, P, ph, pl, EMBED, 0);

    // 2) G = scale * P_h^T P_h
    head_gram_part<<<dim3((M / SEQ) * NHEADS, GCHUNKS), blk>>>(P, Gp);
    gram_reduce<<<(32 * HDIM * HDIM + 255) / 256, blk>>>(Gp, G, 1.0f / 32.0f);

    // 3) B2[b] = blockdiag(G) @ W_out^T
    w2_build<<<dim3(1024 / 64, NHEADS, M / SEQ), blk>>>(W_out, G, b2h, b2l);

    // 4) out = P @ B2[b]^T + b_out
    gemm_mma_bf16x3<<<dim3(1024 / BN, M / BM), blk, SMEM_BYTES>>>(
        ph, pl, b2h, b2l, b_out, out, nullptr, nullptr, NCLS, (long)1024 * EMBED);
}

// round 9
// speedup vs baseline: 1.1856x; 1.0643x over previous
#include <cuda_runtime.h>
#include <cuda_bf16.h>

#define EMBED 1024
#define NHEADS 16
#define HDIM 64
#define SEQ 2048
#define NCLS 1000
#define GCHUNKS 8
#define MTOT 4096

#define BM 128
#define BN 128
#define BKE 32
#define NIT (EMBED / BKE)         // 32
#define PK 40                     // padded row: 80B, ldmatrix conflict-free
#define TSZ (BM * PK)
#define STAGEB (4 * TSZ * 2)      // 40960 B
#define SMEM_BYTES (2 * STAGEB)   // 81920 -> 2 CTAs/SM

// ---------- scratch ----------
__device__ float g_G[32 * HDIM * HDIM];
__device__ float g_Gpart[GCHUNKS][32][HDIM * HDIM];
__device__ __nv_bfloat16 g_xh[MTOT * EMBED], g_xl[MTOT * EMBED];
__device__ __nv_bfloat16 g_wih[EMBED * EMBED], g_wil[EMBED * EMBED];
__device__ __nv_bfloat16 g_ph[MTOT * EMBED], g_pl[MTOT * EMBED];
__device__ __nv_bfloat16 g_b2h[2 * 1024 * EMBED], g_b2l[2 * 1024 * EMBED];

// ---------- helpers ----------
__device__ __forceinline__ unsigned smem_u32(const void* p) {
    unsigned a;
    asm("{ .reg .u64 t; cvta.to.shared.u64 t, %1; cvt.u32.u64 %0, t; }" : "=r"(a) : "l"(p));
    return a;
}
__device__ __forceinline__ void cpa16(unsigned s, const void* g) {
    asm volatile("cp.async.cg.shared.global [%0], [%1], 16;" :: "r"(s), "l"(g) : "memory");
}
#define CP_COMMIT() asm volatile("cp.async.commit_group;" ::: "memory")
#define CP_WAIT(n)  asm volatile("cp.async.wait_group %0;" :: "n"(n) : "memory")

#define LDSM4(r0, r1, r2, r3, a) \
    asm volatile("ldmatrix.sync.aligned.m8n8.x4.shared.b16 {%0,%1,%2,%3}, [%4];" \
        : "=r"(r0), "=r"(r1), "=r"(r2), "=r"(r3) : "r"(a))

#define LDSM4T(r0, r1, r2, r3, a) \
    asm volatile("ldmatrix.sync.aligned.m8n8.x4.trans.shared.b16 {%0,%1,%2,%3}, [%4];" \
        : "=r"(r0), "=r"(r1), "=r"(r2), "=r"(r3) : "r"(a))

#define MMA(c, a, b0v, b1v) \
    asm volatile("mma.sync.aligned.m16n8k16.row.col.f32.bf16.bf16.f32 " \
        "{%0,%1,%2,%3},{%4,%5,%6,%7},{%8,%9},{%0,%1,%2,%3};" \
        : "+f"((c)[0]), "+f"((c)[1]), "+f"((c)[2]), "+f"((c)[3]) \
        : "r"((a)[0]), "r"((a)[1]), "r"((a)[2]), "r"((a)[3]), "r"(b0v), "r"(b1v))

__device__ __forceinline__ unsigned pack_bf(float e0, float e1) {
    unsigned r;
    asm("cvt.rn.bf16x2.f32 %0, %1, %2;" : "=r"(r) : "f"(e1), "f"(e0));
    return r;
}

// ---------- fp32 -> (hi, lo) bf16 split ----------
__global__ void cvt_split(const float4* __restrict__ X, uint2* __restrict__ H,
                          uint2* __restrict__ L, int n4) {
    int i = blockIdx.x * blockDim.x + threadIdx.x;
    if (i >= n4) return;
    float4 x = X[i];
    unsigned h01 = pack_bf(x.x, x.y), h23 = pack_bf(x.z, x.w);
    float hx = __uint_as_float(h01 << 16), hy = __uint_as_float(h01 & 0xffff0000u);
    float hz = __uint_as_float(h23 << 16), hw = __uint_as_float(h23 & 0xffff0000u);
    unsigned l01 = pack_bf(x.x - hx, x.y - hy), l23 = pack_bf(x.z - hz, x.w - hw);
    H[i] = make_uint2(h01, h23);
    L[i] = make_uint2(l01, l23);
}

// ---------- bf16x3 mma.sync GEMM ----------
__device__ __forceinline__ void load_stage(
    unsigned sbuf, int tid, int k0,
    const __nv_bfloat16* Ah, const __nv_bfloat16* Al,
    const __nv_bfloat16* Bh, const __nv_bfloat16* Bl,
    int m0, int n0)
{
    int row = tid >> 1;
    int half = tid & 1;
    unsigned soff = (unsigned)(row * PK + half * 16) * 2;
    size_t ga = (size_t)(m0 + row) * EMBED + k0 + half * 16;
    size_t gb = (size_t)(n0 + row) * EMBED + k0 + half * 16;
    cpa16(sbuf + soff,                Ah + ga);
    cpa16(sbuf + soff + 16,           Ah + ga + 8);
    cpa16(sbuf + TSZ * 2 + soff,      Al + ga);
    cpa16(sbuf + TSZ * 2 + soff + 16, Al + ga + 8);
    cpa16(sbuf + TSZ * 4 + soff,      Bh + gb);
    cpa16(sbuf + TSZ * 4 + soff + 16, Bh + gb + 8);
    cpa16(sbuf + TSZ * 6 + soff,      Bl + gb);
    cpa16(sbuf + TSZ * 6 + soff + 16, Bl + gb + 8);
}

__global__ __launch_bounds__(256, 2) void gemm_mma_bf16x3(
    const __nv_bfloat16* __restrict__ Ah, const __nv_bfloat16* __restrict__ Al,
    const __nv_bfloat16* __restrict__ BhBase, const __nv_bfloat16* __restrict__ BlBase,
    const float* __restrict__ bias, float* __restrict__ C,
    __nv_bfloat16* __restrict__ Sh, __nv_bfloat16* __restrict__ Sl,
    int N, long bStride)
{
    extern __shared__ __nv_bfloat16 sm[];
    int tid = threadIdx.x;
    int m0 = blockIdx.y * BM;
    int n0 = blockIdx.x * BN;
    unsigned sbase = smem_u32(sm);

    const __nv_bfloat16* Bh = BhBase + (size_t)(m0 >> 11) * bStride;
    const __nv_bfloat16* Bl = BlBase + (size_t)(m0 >> 11) * bStride;

    int wid = tid >> 5, lane = tid & 31;
    int wm = (wid & 1) * 64;
    int wn = (wid >> 1) * 32;

    float acc[4][4][4];
#pragma unroll
    for (int i = 0; i < 4; i++)
#pragma unroll
        for (int j = 0; j < 4; j++)
#pragma unroll
            for (int v = 0; v < 4; v++) acc[i][j][v] = 0.f;

    load_stage(sbase, tid, 0, Ah, Al, Bh, Bl, m0, n0);
    CP_COMMIT();

    unsigned a_lo = (unsigned)((wm + (lane & 15)) * PK + ((lane >> 4) << 3)) * 2;
    unsigned b_lo = (unsigned)((wn + (lane & 15)) * PK + ((lane >> 4) << 3)) * 2;

    for (int it = 0; it < NIT; it++) {
        CP_WAIT(0);
        __syncthreads();
        if (it + 1 < NIT) {
            load_stage(sbase + (unsigned)((it + 1) & 1) * STAGEB, tid,
                       (it + 1) * BKE, Ah, Al, Bh, Bl, m0, n0);
            CP_COMMIT();
        }

        unsigned sbuf = sbase + (unsigned)(it & 1) * STAGEB;
#pragma unroll
        for (int kk = 0; kk < 2; kk++) {
            unsigned ah[4][4], al[4][4], bb[2][4];
            unsigned ao = sbuf + a_lo + (unsigned)kk * 32;
            unsigned bo = sbuf + b_lo + (unsigned)kk * 32;

#pragma unroll
            for (int i = 0; i < 4; i++)
                LDSM4(ah[i][0], ah[i][1], ah[i][2], ah[i][3], ao + (unsigned)i * (16 * PK * 2));
#pragma unroll
            for (int L = 0; L < 2; L++)
                LDSM4(bb[L][0], bb[L][1], bb[L][2], bb[L][3], bo + TSZ * 4 + (unsigned)L * (16 * PK * 2));
#pragma unroll
            for (int i = 0; i < 4; i++)
#pragma unroll
                for (int j = 0; j < 4; j++) {
                    int L = j >> 1, s = j & 1;
                    MMA(acc[i][j], ah[i], bb[L][s], bb[L][s + 2]);
                }
#pragma unroll
            for (int i = 0; i < 4; i++)
                LDSM4(al[i][0], al[i][1], al[i][2], al[i][3], ao + TSZ * 2 + (unsigned)i * (16 * PK * 2));
#pragma unroll
            for (int i = 0; i < 4; i++)
#pragma unroll
                for (int j = 0; j < 4; j++) {
                    int L = j >> 1, s = j & 1;
                    MMA(acc[i][j], al[i], bb[L][s], bb[L][s + 2]);
                }
#pragma unroll
            for (int L = 0; L < 2; L++)
                LDSM4(bb[L][0], bb[L][1], bb[L][2], bb[L][3], bo + TSZ * 6 + (unsigned)L * (16 * PK * 2));
#pragma unroll
            for (int i = 0; i < 4; i++)
#pragma unroll
                for (int j = 0; j < 4; j++) {
                    int L = j >> 1, s = j & 1;
                    MMA(acc[i][j], ah[i], bb[L][s], bb[L][s + 2]);
                }
        }
    }

    // epilogue
    int r = lane >> 2, c2 = (lane & 3) * 2;
#pragma unroll
    for (int i = 0; i < 4; i++) {
        int m = m0 + wm + i * 16 + r;
#pragma unroll
        for (int j = 0; j < 4; j++) {
            int n = n0 + wn + j * 8 + c2;
            float bv0 = (n < N) ? bias[n] : 0.f;
            float bv1 = (n + 1 < N) ? bias[n + 1] : 0.f;
            float v00 = acc[i][j][0] + bv0, v01 = acc[i][j][1] + bv1;
            float v10 = acc[i][j][2] + bv0, v11 = acc[i][j][3] + bv1;
            if (C) {
                float* C0 = C + (size_t)m * N;
                float* C1 = C0 + (size_t)8 * N;
                if (n < N)     { C0[n] = v00; C1[n] = v10; }
                if (n + 1 < N) { C0[n + 1] = v01; C1[n + 1] = v11; }
            }
            if (Sh) {
                unsigned* S0h = (unsigned*)(Sh + (size_t)m * EMBED);
                unsigned* S0l = (unsigned*)(Sl + (size_t)m * EMBED);
                unsigned* S1h = (unsigned*)(Sh + (size_t)(m + 8) * EMBED);
                unsigned* S1l = (unsigned*)(Sl + (size_t)(m + 8) * EMBED);
                unsigned h0 = pack_bf(v00, v01);
                unsigned h1 = pack_bf(v10, v11);
                float h0x = __uint_as_float(h0 << 16), h0y = __uint_as_float(h0 & 0xffff0000u);
                float h1x = __uint_as_float(h1 << 16), h1y = __uint_as_float(h1 & 0xffff0000u);
                S0h[n >> 1] = h0;
                S1h[n >> 1] = h1;
                S0l[n >> 1] = pack_bf(v00 - h0x, v01 - h0y);
                S1l[n >> 1] = pack_bf(v10 - h1x, v11 - h1y);
            }
        }
    }
}

// ---------- tensor-core Gram: Gpart[chunk][bh] = P_h^T P_h over 256 s-rows ----------
// Uses ph/pl (bf16 hi/lo), 3-term. ldmatrix.trans gives both A (=tile^T) and B frags.
#define GPD 72   // padded row (bf16): 144B -> conflict-free trans ldmatrix

__global__ __launch_bounds__(256, 2) void head_gram_mma(
    const __nv_bfloat16* __restrict__ ph, const __nv_bfloat16* __restrict__ pl,
    float* __restrict__ Gpart)
{
    __shared__ __nv_bfloat16 sh[128][GPD];
    __shared__ __nv_bfloat16 sl[128][GPD];

    int bh = blockIdx.x;               // 0..31
    int chunk = blockIdx.y;            // 0..7
    int b = bh >> 4;
    int h = bh & 15;
    int tid = threadIdx.x;
    int wid = tid >> 5, lane = tid & 31;
    int wm = (wid & 1) * 32;           // d1 offset
    int wn = (wid >> 1) * 16;          // d2 offset

    unsigned shB = smem_u32(&sh[0][0]);
    unsigned slB = smem_u32(&sl[0][0]);

    // trans-ldmatrix lane offsets
    int g = lane >> 3, l = lane & 7;
    unsigned aRowOff = (unsigned)(((g & 2) ? 8 : 0) + l) * (GPD * 2);
    unsigned aColOff = (unsigned)(wm + ((g & 1) ? 8 : 0)) * 2;
    unsigned bRowOff = (unsigned)(((g & 1) ? 8 : 0) + l) * (GPD * 2);
    unsigned bColOff = (unsigned)(wn + ((g >= 2) ? 8 : 0)) * 2;

    float acc[2][2][4];
#pragma unroll
    for (int i = 0; i < 2; i++)
#pragma unroll
        for (int j = 0; j < 2; j++)
#pragma unroll
            for (int v = 0; v < 4; v++) acc[i][j][v] = 0.f;

    int row = tid >> 1;                 // 0..127
    int q = tid & 1;                    // 32-elem half
    unsigned soff = (unsigned)(row * GPD + q * 32) * 2;

    for (int half = 0; half < 2; half++) {
        // load 128 x 64 tiles of ph, pl
        size_t gbase = (size_t)(b * SEQ + chunk * 256 + half * 128 + row) * EMBED + h * HDIM + q * 32;
#pragma unroll
        for (int t = 0; t < 4; t++) {
            cpa16(shB + soff + t * 16, ph + gbase + t * 8);
            cpa16(slB + soff + t * 16, pl + gbase + t * 8);
        }
        CP_COMMIT();
        CP_WAIT(0);
        __syncthreads();

#pragma unroll
        for (int k0 = 0; k0 < 128; k0 += 16) {
            unsigned kb = (unsigned)k0 * (GPD * 2);
            unsigned Ah2[2][4], Al2[2][4], Bh4[4], Bl4[4];
#pragma unroll
            for (int i = 0; i < 2; i++) {
                LDSM4T(Ah2[i][0], Ah2[i][1], Ah2[i][2], Ah2[i][3],
                       shB + kb + aRowOff + aColOff + (unsigned)i * 32);
                LDSM4T(Al2[i][0], Al2[i][1], Al2[i][2], Al2[i][3],
                       slB + kb + aRowOff + aColOff + (unsigned)i * 32);
            }
            LDSM4T(Bh4[0], Bh4[1], Bh4[2], Bh4[3], shB + kb + bRowOff + bColOff);
            LDSM4T(Bl4[0], Bl4[1], Bl4[2], Bl4[3], slB + kb + bRowOff + bColOff);

#pragma unroll
            for (int i = 0; i < 2; i++)
#pragma unroll
                for (int j = 0; j < 2; j++) {
                    MMA(acc[i][j], Ah2[i], Bh4[j * 2], Bh4[j * 2 + 1]);
                    MMA(acc[i][j], Ah2[i], Bl4[j * 2], Bl4[j * 2 + 1]);
                    MMA(acc[i][j], Al2[i], Bh4[j * 2], Bh4[j * 2 + 1]);
                }
        }
        __syncthreads();   // done reading before next half overwrites
    }

    float* Gp = Gpart + ((size_t)chunk * 32 + bh) * (HDIM * HDIM);
    int r = lane >> 2, c2 = (lane & 3) * 2;
#pragma unroll
    for (int i = 0; i < 2; i++) {
        int d1a = wm + i * 16 + r;
#pragma unroll
        for (int j = 0; j < 2; j++) {
            int d2 = wn + j * 8 + c2;
            Gp[d1a * HDIM + d2]           = acc[i][j][0];
            Gp[d1a * HDIM + d2 + 1]       = acc[i][j][1];
            Gp[(d1a + 8) * HDIM + d2]     = acc[i][j][2];
            Gp[(d1a + 8) * HDIM + d2 + 1] = acc[i][j][3];
        }
    }
}

__global__ void gram_reduce(const float* __restrict__ Gpart,
                            float* __restrict__ G, float scale)
{
    int idx = blockIdx.x * blockDim.x + threadIdx.x;
    if (idx >= 32 * HDIM * HDIM) return;
    float s = 0.f;
#pragma unroll
    for (int c = 0; c < GCHUNKS; c++)
        s += Gpart[(size_t)c * 32 * HDIM * HDIM + idx];
    G[idx] = s * scale;
}

// ---------- fused B2 build ----------
__global__ __launch_bounds__(256) void w2_build(
    const float* __restrict__ Wo, const float* __restrict__ G,
    __nv_bfloat16* __restrict__ B2h, __nv_bfloat16* __restrict__ B2l)
{
    int c0 = blockIdx.x * 64;
    int h  = blockIdx.y;
    int b  = blockIdx.z;
    const float* Gh = G + (size_t)(b * NHEADS + h) * HDIM * HDIM;

    __shared__ float Gs[64][65];
    __shared__ float Ws[64][65];
    int tid = threadIdx.x;

#pragma unroll
    for (int v = 0; v < 4; v++) {
        int idx = tid + v * 256;
        int rr = idx >> 4;
        int c = (idx & 15) << 2;
        float4 g4 = *(const float4*)(Gh + rr * HDIM + c);
        Gs[rr][c + 0] = g4.x; Gs[rr][c + 1] = g4.y;
        Gs[rr][c + 2] = g4.z; Gs[rr][c + 3] = g4.w;
        float4 w4 = make_float4(0.f, 0.f, 0.f, 0.f);
        if (c0 + rr < NCLS)
            w4 = *(const float4*)(Wo + (size_t)(c0 + rr) * EMBED + h * HDIM + c);
        Ws[rr][c + 0] = w4.x; Ws[rr][c + 1] = w4.y;
        Ws[rr][c + 2] = w4.z; Ws[rr][c + 3] = w4.w;
    }
    __syncthreads();

    int j  = tid & 63;
    int i0 = (tid >> 6) << 4;
    float acc[16];
#pragma unroll
    for (int ii = 0; ii < 16; ii++) acc[ii] = 0.f;

#pragma unroll 4
    for (int k = 0; k < 64; k++) {
        float g = Gs[k][j];
#pragma unroll
        for (int ii = 0; ii < 16; ii++)
            acc[ii] += Ws[i0 + ii][k] * g;
    }

#pragma unroll
    for (int ii = 0; ii < 16; ii++) {
        size_t o = (size_t)b * 1024 * EMBED + (size_t)(c0 + i0 + ii) * EMBED + h * HDIM + j;
        float v = acc[ii];
        __nv_bfloat16 hi = __float2bfloat16(v);
        B2h[o] = hi;
        B2l[o] = __float2bfloat16(v - __bfloat162float(hi));
    }
}

// ---------- launch ----------
extern "C" void kernel_launch(void* const* d_in, const int* in_sizes, int n_in,
                              void* d_out, int out_size)
{
    const float* x     = (const float*)d_in[0];
    const float* W_in  = (const float*)d_in[1];
    const float* b_in  = (const float*)d_in[2];
    const float* W_out = (const float*)d_in[3];
    const float* b_out = (const float*)d_in[4];
    float* out = (float*)d_out;

    int M = in_sizes[0] / EMBED;   // 4096

    float *G, *Gp;
    cudaGetSymbolAddress((void**)&G, g_G);
    cudaGetSymbolAddress((void**)&Gp, g_Gpart);
    __nv_bfloat16 *xh, *xl, *wih, *wil, *ph, *pl, *b2h, *b2l;
    cudaGetSymbolAddress((void**)&xh, g_xh);
    cudaGetSymbolAddress((void**)&xl, g_xl);
    cudaGetSymbolAddress((void**)&wih, g_wih);
    cudaGetSymbolAddress((void**)&wil, g_wil);
    cudaGetSymbolAddress((void**)&ph, g_ph);
    cudaGetSymbolAddress((void**)&pl, g_pl);
    cudaGetSymbolAddress((void**)&b2h, g_b2h);
    cudaGetSymbolAddress((void**)&b2l, g_b2l);

    cudaFuncSetAttribute(gemm_mma_bf16x3, cudaFuncAttributeMaxDynamicSharedMemorySize, SMEM_BYTES);

    dim3 blk(256);

    cvt_split<<<(M * EMBED / 4) / 256, blk>>>((const float4*)x, (uint2*)xh, (uint2*)xl, M * EMBED / 4);
    cvt_split<<<(EMBED * EMBED / 4) / 256, blk>>>((const float4*)W_in, (uint2*)wih, (uint2*)wil, EMBED * EMBED / 4);

    // 1) P = X @ W_in^T + b_in  -> hi/lo bf16 only (no fp32 P)
    gemm_mma_bf16x3<<<dim3(EMBED / BN, M / BM), blk, SMEM_BYTES>>>(
        xh, xl, wih, wil, b_in, nullptr, ph, pl, EMBED, 0);

    // 2) G = scale * P_h^T P_h  (tensor cores on ph/pl; scale=1/32)
    head_gram_mma<<<dim3(32, GCHUNKS), blk>>>(ph, pl, Gp);
    gram_reduce<<<(32 * HDIM * HDIM + 255) / 256, blk>>>(Gp, G, 1.0f / 32.0f);

    // 3) B2[b] = blockdiag(G) @ W_out^T
    w2_build<<<dim3(1024 / 64, NHEADS, M / SEQ), blk>>>(W_out, G, b2h, b2l);

    // 4) out = P @ B2[b]^T + b_out
    gemm_mma_bf16x3<<<dim3(1024 / BN, M / BM), blk, SMEM_BYTES>>>(
        ph, pl, b2h, b2l, b_out, out, nullptr, nullptr, NCLS, (long)1024 * EMBED);
}